// round 16
// baseline (speedup 1.0000x reference)
#include <cuda_runtime.h>
#include <cuda_bf16.h>
#include <math.h>
#include <stdint.h>

#define DIM    768
#define DSTATE 16
#define DCONV  4
#define EE     1536          // expand dim
#define BB     2
#define LL     2048
#define BL     (BB*LL)       // 4096
#define EPS    1e-6f

#define CH     16            // chunk length
#define NCH    (LL/CH)       // 128 chunks

// ---------------- scratch (static device arrays; no allocations) -------------
__device__ float          g_xp  [BL * EE];              // after in-proj (fp32)
__device__ float          g_hloc[BB * NCH * DSTATE * EE];   // per-chunk final g
__device__ float          g_hin [BB * NCH * DSTATE * EE];   // per-chunk incoming g
__device__ __nv_bfloat16  g_xnh [BL * DIM];             // rmsnorm out hi
__device__ __nv_bfloat16  g_xnl [BL * DIM];             // rmsnorm out lo
__device__ __nv_bfloat16  g_winh[EE * DIM];
__device__ __nv_bfloat16  g_winl[EE * DIM];
__device__ __nv_bfloat16  g_wouth[DIM * EE];
__device__ __nv_bfloat16  g_woutl[DIM * EE];
__device__ __nv_bfloat16  g_yh  [BL * EE];              // final scan out hi
__device__ __nv_bfloat16  g_yl  [BL * EE];              // final scan out lo

__device__ __forceinline__ float sigmoidf_(float v) {
    return 1.0f / (1.0f + expf(-v));
}

__device__ __forceinline__ uint32_t smem_u32_(const void* p) {
    uint32_t a;
    asm("{ .reg .u64 t; cvta.to.shared.u64 t, %1; cvt.u32.u64 %0, t; }"
        : "=r"(a) : "l"(p));
    return a;
}

// ---------------- rmsnorm (writes bf16 hi/lo split) --------------------------
__global__ void rmsnorm_kernel(const float* __restrict__ x,
                               const float* __restrict__ gamma,
                               __nv_bfloat16* __restrict__ xnh,
                               __nv_bfloat16* __restrict__ xnl)
{
    const int row = blockIdx.x;
    const float* xr = x + (size_t)row * DIM;

    float v0 = xr[threadIdx.x];
    float v1 = xr[threadIdx.x + 256];
    float v2 = xr[threadIdx.x + 512];
    float ss = v0 * v0 + v1 * v1 + v2 * v2;

    #pragma unroll
    for (int o = 16; o > 0; o >>= 1)
        ss += __shfl_xor_sync(0xffffffffu, ss, o);

    __shared__ float warp_s[8];
    int wid = threadIdx.x >> 5, lane = threadIdx.x & 31;
    if (lane == 0) warp_s[wid] = ss;
    __syncthreads();
    if (wid == 0) {
        float t = (lane < 8) ? warp_s[lane] : 0.f;
        #pragma unroll
        for (int o = 4; o > 0; o >>= 1)
            t += __shfl_xor_sync(0xffffffffu, t, o);
        if (lane == 0) warp_s[0] = t;
    }
    __syncthreads();
    float rms = sqrtf(warp_s[0] * (1.0f / DIM));
    float inv = 1.0f / (rms + EPS);

    #pragma unroll
    for (int k = 0; k < 3; k++) {
        int i = threadIdx.x + k * 256;
        float v = (k == 0) ? v0 : (k == 1) ? v1 : v2;
        float o = gamma[i] * v * inv;
        __nv_bfloat16 h = __float2bfloat16(o);
        xnh[(size_t)row * DIM + i] = h;
        xnl[(size_t)row * DIM + i] = __float2bfloat16(o - __bfloat162float(h));
    }
}

// ---------------- weight conversion fp32 -> bf16 hi/lo (float4) --------------
__global__ void convert_w_kernel(const float* __restrict__ W_in,
                                 const float* __restrict__ W_out,
                                 __nv_bfloat16* __restrict__ winh,
                                 __nv_bfloat16* __restrict__ winl,
                                 __nv_bfloat16* __restrict__ wouth,
                                 __nv_bfloat16* __restrict__ woutl)
{
    const int SZ = EE * DIM;                 // multiple of 4
    int q = blockIdx.x * blockDim.x + threadIdx.x;   // float4 index
    if (q >= (2 * SZ) / 4) return;
    int j4 = q * 4;
    const float* s; __nv_bfloat16 *dh, *dl; int j;
    if (j4 < SZ) { s = W_in;  j = j4;      dh = winh;  dl = winl;  }
    else         { s = W_out; j = j4 - SZ; dh = wouth; dl = woutl; }

    float4 v = *(const float4*)&s[j];
    __nv_bfloat16 h0 = __float2bfloat16(v.x);
    __nv_bfloat16 h1 = __float2bfloat16(v.y);
    __nv_bfloat16 h2 = __float2bfloat16(v.z);
    __nv_bfloat16 h3 = __float2bfloat16(v.w);
    __nv_bfloat16 hv[4] = { h0, h1, h2, h3 };
    __nv_bfloat16 lv[4] = {
        __float2bfloat16(v.x - __bfloat162float(h0)),
        __float2bfloat16(v.y - __bfloat162float(h1)),
        __float2bfloat16(v.z - __bfloat162float(h2)),
        __float2bfloat16(v.w - __bfloat162float(h3))
    };
    *(uint2*)&dh[j] = *(const uint2*)hv;
    *(uint2*)&dl[j] = *(const uint2*)lv;
}

// ======================= HMMA (mma.sync) GEMM ================================
// (unchanged from round 15 — passing)
// CTA tile 64x128x32, 256 threads, 8 warps (2x4), warp tile 32x32.
#define BKT    32
#define PADR   40
#define APLANE (64 * PADR)
#define BPLANE (128 * PADR)
#define STAGE  (2 * APLANE + 2 * BPLANE)
#define SMEM_GEMM (2 * STAGE * 2)      // 61440 bytes

__device__ __forceinline__ void mma16816(float* d, const uint32_t* a, const uint32_t* b) {
    asm volatile(
        "mma.sync.aligned.m16n8k16.row.col.f32.bf16.bf16.f32 "
        "{%0,%1,%2,%3}, {%4,%5,%6,%7}, {%8,%9}, {%0,%1,%2,%3};"
        : "+f"(d[0]), "+f"(d[1]), "+f"(d[2]), "+f"(d[3])
        : "r"(a[0]), "r"(a[1]), "r"(a[2]), "r"(a[3]), "r"(b[0]), "r"(b[1]));
}

__device__ __forceinline__ void ldsm4(uint32_t* r, uint32_t addr) {
    asm volatile("ldmatrix.sync.aligned.m8n8.x4.shared.b16 {%0,%1,%2,%3}, [%4];"
                 : "=r"(r[0]), "=r"(r[1]), "=r"(r[2]), "=r"(r[3]) : "r"(addr));
}

#define CP_ASYNC16(s, g) asm volatile("cp.async.cg.shared.global [%0], [%1], 16;" :: "r"(s), "l"(g))
#define CP_COMMIT()      asm volatile("cp.async.commit_group;")
#define CP_WAIT1()       asm volatile("cp.async.wait_group 1;")

template<bool RESID>
__global__ __launch_bounds__(256, 3)
void gemm_mma_kernel(const __nv_bfloat16* __restrict__ Ah,
                     const __nv_bfloat16* __restrict__ Al,
                     const __nv_bfloat16* __restrict__ Bh,
                     const __nv_bfloat16* __restrict__ Bl,
                     const float* __restrict__ bias,
                     const float* __restrict__ resid,
                     float* __restrict__ Cout,
                     int N, int K)
{
    extern __shared__ __nv_bfloat16 sm[];
    const uint32_t sm32 = smem_u32_(sm);
    const int tid  = threadIdx.x;
    const int wid  = tid >> 5, lane = tid & 31;
    const int g    = lane >> 2;
    const int t2   = (lane & 3) * 2;
    const int brow = blockIdx.y * 64, bcol = blockIdx.x * 128;
    const int warp_m = (wid >> 2) * 32;
    const int warp_n = (wid & 3) * 32;

    const __nv_bfloat16* gptr[4] = { Ah, Al, Bh, Bl };

    const int arow  = (lane & 7) + 8 * ((lane >> 3) & 1);
    const int akofs = 8 * (lane >> 4);
    const uint32_t a_off = (uint32_t)((warp_m + arow) * PADR + akofs) * 2;
    const int browl = (lane & 7) + 8 * (lane >> 4);
    const int bkofs = 8 * ((lane >> 3) & 1);
    const uint32_t b_off = (uint32_t)((warp_n + browl) * PADR + bkofs) * 2;

    float acc[2][4][4];
    #pragma unroll
    for (int mt = 0; mt < 2; mt++)
        #pragma unroll
        for (int nt = 0; nt < 4; nt++)
            #pragma unroll
            for (int q = 0; q < 4; q++) acc[mt][nt][q] = 0.f;

    auto issue = [&](int st, int kt) {
        uint32_t sb = sm32 + (uint32_t)st * STAGE * 2;
        #pragma unroll
        for (int q = 0; q < 6; q++) {
            int ch = tid + q * 256;
            int r, rbase;
            uint32_t pofs;
            const __nv_bfloat16* gp;
            if (ch < 512) {
                int pa = ch >> 8;
                int rc = ch & 255;
                r = rc >> 2;
                pofs = (uint32_t)(pa * APLANE);
                gp = gptr[pa];
                rbase = brow;
            } else {
                int cb = ch - 512;
                int pb = cb >> 9;
                int rc = cb & 511;
                r = rc >> 2;
                pofs = (uint32_t)(2 * APLANE + pb * BPLANE);
                gp = gptr[2 + pb];
                rbase = bcol;
            }
            int c = (ch & 3) * 8;
            uint32_t sa = sb + (pofs + (uint32_t)(r * PADR + c)) * 2;
            const __nv_bfloat16* ga = gp + (size_t)(rbase + r) * K + kt + c;
            CP_ASYNC16(sa, ga);
        }
        CP_COMMIT();
    };

    const int NK = K / BKT;
    issue(0, 0);
    issue(1, BKT);
    CP_WAIT1();
    __syncthreads();

    for (int i = 0; i < NK; i++) {
        const int st = i & 1;
        const uint32_t sbase = sm32 + (uint32_t)st * STAGE * 2;

        #pragma unroll
        for (int kk = 0; kk < BKT; kk += 16) {
            const uint32_t kb = (uint32_t)kk * 2;
            uint32_t ah[2][4], al[2][4], bh[2][4], bl[2][4];
            #pragma unroll
            for (int mt = 0; mt < 2; mt++) {
                uint32_t ad = sbase + a_off + (uint32_t)(mt * 16 * PADR) * 2 + kb;
                ldsm4(ah[mt], ad);
                ldsm4(al[mt], ad + (uint32_t)APLANE * 2);
            }
            #pragma unroll
            for (int ntp = 0; ntp < 2; ntp++) {
                uint32_t bd = sbase + b_off
                            + (uint32_t)(2 * APLANE + ntp * 16 * PADR) * 2 + kb;
                ldsm4(bh[ntp], bd);
                ldsm4(bl[ntp], bd + (uint32_t)BPLANE * 2);
            }

            #pragma unroll
            for (int mt = 0; mt < 2; mt++)
                #pragma unroll
                for (int nt = 0; nt < 4; nt++) {
                    const uint32_t* fh = &bh[nt >> 1][(nt & 1) * 2];
                    const uint32_t* fl = &bl[nt >> 1][(nt & 1) * 2];
                    mma16816(acc[mt][nt], ah[mt], fh);
                    mma16816(acc[mt][nt], ah[mt], fl);
                    mma16816(acc[mt][nt], al[mt], fh);
                }
        }

        __syncthreads();
        if (i + 2 < NK) issue(st, (i + 2) * BKT);
        else            CP_COMMIT();
        CP_WAIT1();
        __syncthreads();
    }

    #pragma unroll
    for (int mt = 0; mt < 2; mt++) {
        int r0 = brow + warp_m + mt * 16 + g;
        #pragma unroll
        for (int nt = 0; nt < 4; nt++) {
            int c = bcol + warp_n + nt * 8 + t2;
            float2 bv = *(const float2*)&bias[c];
            float2 o0, o1;
            o0.x = acc[mt][nt][0] + bv.x;
            o0.y = acc[mt][nt][1] + bv.y;
            o1.x = acc[mt][nt][2] + bv.x;
            o1.y = acc[mt][nt][3] + bv.y;
            if (RESID) {
                float2 rv0 = *(const float2*)&resid[(size_t)r0 * N + c];
                float2 rv1 = *(const float2*)&resid[(size_t)(r0 + 8) * N + c];
                o0.x += rv0.x; o0.y += rv0.y;
                o1.x += rv1.x; o1.y += rv1.y;
            }
            *(float2*)&Cout[(size_t)r0 * N + c]       = o0;
            *(float2*)&Cout[(size_t)(r0 + 8) * N + c] = o1;
        }
    }
}

// ---------------- K1: per-chunk final g-states (conv fused) ------------------
__global__ __launch_bounds__(256)
void scan_state_kernel(const float* __restrict__ xp,
                       const float* __restrict__ A,
                       const float* __restrict__ convw,
                       float* __restrict__ hloc)
{
    int tid = blockIdx.x * blockDim.x + threadIdx.x;   // b*NCH*EE + c*EE + e
    int e  = tid % EE;
    int bc = tid / EE;
    int c  = bc % NCH;
    int b  = bc / NCH;

    float sA[DSTATE], g[DSTATE];
    #pragma unroll
    for (int n = 0; n < DSTATE; n++) {
        sA[n] = sigmoidf_(A[e * DSTATE + n]);
        g[n] = 0.f;
    }
    float w0 = convw[e * 4 + 0];
    float w1 = convw[e * 4 + 1];
    float w2 = convw[e * 4 + 2];
    float w3 = convw[e * 4 + 3];

    const int t0 = c * CH;
    const float* xb = xp + (size_t)b * LL * EE + e;
    float xm1 = (t0 >= 1) ? xb[(size_t)(t0 - 1) * EE] : 0.f;
    float xm2 = (t0 >= 2) ? xb[(size_t)(t0 - 2) * EE] : 0.f;
    float xm3 = (t0 >= 3) ? xb[(size_t)(t0 - 3) * EE] : 0.f;

    const float* xq = xb + (size_t)t0 * EE;

    #pragma unroll
    for (int tb = 0; tb < CH; tb += 8) {
        float xv[8];
        #pragma unroll
        for (int j = 0; j < 8; j++)
            xv[j] = xq[(size_t)(tb + j) * EE];

        #pragma unroll
        for (int j = 0; j < 8; j++) {
            float xcv = xv[j] * w3 + xm1 * w2 + xm2 * w1 + xm3 * w0;
            xm3 = xm2; xm2 = xm1; xm1 = xv[j];
            #pragma unroll
            for (int n = 0; n < DSTATE; n++)
                g[n] = fmaf(sA[n], g[n], xcv);
        }
    }

    float* hp = hloc + (((size_t)b * NCH + c) * DSTATE) * EE + e;
    #pragma unroll
    for (int n = 0; n < DSTATE; n++)
        hp[(size_t)n * EE] = g[n];
}

// ---------------- K2: combine chunk g-states sequentially --------------------
__global__ void chunk_combine_kernel(const float* __restrict__ hloc,
                                     const float* __restrict__ A,
                                     float* __restrict__ hin)
{
    int tid = blockIdx.x * blockDim.x + threadIdx.x;   // b*DSTATE*EE + n*EE + e
    int e  = tid % EE;
    int bn = tid / EE;
    int n  = bn % DSTATE;
    int b  = bn / DSTATE;

    float sA = sigmoidf_(A[e * DSTATE + n]);
    float pw = sA;
    #pragma unroll
    for (int i = 0; i < 4; i++) pw *= pw;              // sA^16 (CH=16)

    size_t base = ((size_t)b * NCH * DSTATE + n) * EE + e;
    const size_t cstride = (size_t)DSTATE * EE;

    float h = 0.f;
    #pragma unroll 16
    for (int c = 0; c < NCH; c++) {
        hin[base + c * cstride] = h;
        h = fmaf(pw, h, hloc[base + c * cstride]);
    }
}

// ---------------- K3: full g-scan from hin, y = sum sCB*g, bf16 split --------
__global__ __launch_bounds__(256)
void scan_out_kernel(const float* __restrict__ xp,
                     const float* __restrict__ hin,
                     const float* __restrict__ A,
                     const float* __restrict__ Bp,
                     const float* __restrict__ C,
                     const float* __restrict__ convw,
                     __nv_bfloat16* __restrict__ yh,
                     __nv_bfloat16* __restrict__ yl)
{
    int tid = blockIdx.x * blockDim.x + threadIdx.x;   // b*NCH*EE + c*EE + e
    int e  = tid % EE;
    int bc = tid / EE;
    int c  = bc % NCH;
    int b  = bc / NCH;

    float sA[DSTATE], sCB[DSTATE], g[DSTATE];
    const float* hp = hin + (((size_t)b * NCH + c) * DSTATE) * EE + e;
    #pragma unroll
    for (int n = 0; n < DSTATE; n++) {
        sA[n]  = sigmoidf_(A[e * DSTATE + n]);
        sCB[n] = sigmoidf_(C[e * DSTATE + n]) * sigmoidf_(Bp[e * DSTATE + n]);
        g[n]   = (c > 0) ? hp[(size_t)n * EE] : 0.f;
    }
    float w0 = convw[e * 4 + 0];
    float w1 = convw[e * 4 + 1];
    float w2 = convw[e * 4 + 2];
    float w3 = convw[e * 4 + 3];

    const int t0 = c * CH;
    const float* xb = xp + (size_t)b * LL * EE + e;
    float xm1 = (t0 >= 1) ? xb[(size_t)(t0 - 1) * EE] : 0.f;
    float xm2 = (t0 >= 2) ? xb[(size_t)(t0 - 2) * EE] : 0.f;
    float xm3 = (t0 >= 3) ? xb[(size_t)(t0 - 3) * EE] : 0.f;

    const float* xq = xb + (size_t)t0 * EE;
    size_t obase = ((size_t)b * LL + t0) * EE + e;
    __nv_bfloat16* yhb = yh + obase;
    __nv_bfloat16* ylb = yl + obase;

    #pragma unroll
    for (int tb = 0; tb < CH; tb += 8) {
        float xv[8];
        #pragma unroll
        for (int j = 0; j < 8; j++)
            xv[j] = xq[(size_t)(tb + j) * EE];

        #pragma unroll
        for (int j = 0; j < 8; j++) {
            float xcv = xv[j] * w3 + xm1 * w2 + xm2 * w1 + xm3 * w0;
            xm3 = xm2; xm2 = xm1; xm1 = xv[j];

            float a0 = 0.f, a1 = 0.f, a2 = 0.f, a3 = 0.f;
            #pragma unroll
            for (int n = 0; n < DSTATE; n += 4) {
                g[n + 0] = fmaf(sA[n + 0], g[n + 0], xcv);
                g[n + 1] = fmaf(sA[n + 1], g[n + 1], xcv);
                g[n + 2] = fmaf(sA[n + 2], g[n + 2], xcv);
                g[n + 3] = fmaf(sA[n + 3], g[n + 3], xcv);
                a0 = fmaf(sCB[n + 0], g[n + 0], a0);
                a1 = fmaf(sCB[n + 1], g[n + 1], a1);
                a2 = fmaf(sCB[n + 2], g[n + 2], a2);
                a3 = fmaf(sCB[n + 3], g[n + 3], a3);
            }
            float v = (a0 + a1) + (a2 + a3);
            __nv_bfloat16 hv = __float2bfloat16(v);
            yhb[(size_t)(tb + j) * EE] = hv;
            ylb[(size_t)(tb + j) * EE] = __float2bfloat16(v - __bfloat162float(hv));
        }
    }
}

// ---------------- launch -----------------------------------------------------
extern "C" void kernel_launch(void* const* d_in, const int* in_sizes, int n_in,
                              void* d_out, int out_size)
{
    const float* x      = (const float*)d_in[0];
    const float* gamma  = (const float*)d_in[1];
    const float* W_in   = (const float*)d_in[2];
    const float* b_in   = (const float*)d_in[3];
    const float* conv_w = (const float*)d_in[4];
    const float* A      = (const float*)d_in[5];
    const float* Bp     = (const float*)d_in[6];
    const float* C      = (const float*)d_in[7];
    const float* W_out  = (const float*)d_in[8];
    const float* b_out  = (const float*)d_in[9];
    float* out = (float*)d_out;

    float *xp, *hloc, *hin;
    __nv_bfloat16 *xnh, *xnl, *winh, *winl, *wouth, *woutl, *yh, *yl;
    cudaGetSymbolAddress((void**)&xp,    g_xp);
    cudaGetSymbolAddress((void**)&hloc,  g_hloc);
    cudaGetSymbolAddress((void**)&hin,   g_hin);
    cudaGetSymbolAddress((void**)&xnh,   g_xnh);
    cudaGetSymbolAddress((void**)&xnl,   g_xnl);
    cudaGetSymbolAddress((void**)&winh,  g_winh);
    cudaGetSymbolAddress((void**)&winl,  g_winl);
    cudaGetSymbolAddress((void**)&wouth, g_wouth);
    cudaGetSymbolAddress((void**)&woutl, g_woutl);
    cudaGetSymbolAddress((void**)&yh,    g_yh);
    cudaGetSymbolAddress((void**)&yl,    g_yl);

    // idempotent, capture-safe, no static state
    cudaFuncSetAttribute(gemm_mma_kernel<false>,
                         cudaFuncAttributeMaxDynamicSharedMemorySize, SMEM_GEMM);
    cudaFuncSetAttribute(gemm_mma_kernel<true>,
                         cudaFuncAttributeMaxDynamicSharedMemorySize, SMEM_GEMM);

    // 1. rmsnorm -> bf16 hi/lo
    rmsnorm_kernel<<<BL, 256>>>(x, gamma, xnh, xnl);

    // 1b. convert weights -> bf16 hi/lo (float4)
    {
        int qtot = (2 * EE * DIM) / 4;                 // 589824
        convert_w_kernel<<<(qtot + 255) / 256, 256>>>(W_in, W_out,
                                                      winh, winl, wouth, woutl);
    }

    // 2. in-proj (HMMA): xp = xn @ W_in^T + b_in
    {
        dim3 grid(EE / 128, BL / 64);
        gemm_mma_kernel<false><<<grid, 256, SMEM_GEMM>>>(xnh, xnl, winh, winl,
                                                         b_in, nullptr, xp, EE, DIM);
    }

    // 3. chunked g-scan (conv fused)
    {
        int threads = BB * NCH * EE;                   // 393216
        scan_state_kernel<<<threads / 256, 256>>>(xp, A, conv_w, hloc);
    }
    {
        int threads = BB * DSTATE * EE;                // 49152
        chunk_combine_kernel<<<threads / 256, 256>>>(hloc, A, hin);
    }
    {
        int threads = BB * NCH * EE;
        scan_out_kernel<<<threads / 256, 256>>>(xp, hin, A, Bp, C, conv_w, yh, yl);
    }

    // 4. out-proj + residual (HMMA): out = y @ W_out^T + b_out + x
    {
        dim3 grid(DIM / 128, BL / 64);
        gemm_mma_kernel<true><<<grid, 256, SMEM_GEMM>>>(yh, yl, wouth, woutl,
                                                        b_out, x, out, DIM, EE);
    }
}

// round 17
// speedup vs baseline: 1.0972x; 1.0972x over previous
#include <cuda_runtime.h>
#include <cuda_bf16.h>
#include <math.h>
#include <stdint.h>

#define DIM    768
#define DSTATE 16
#define DCONV  4
#define EE     1536          // expand dim
#define BB     2
#define LL     2048
#define BL     (BB*LL)       // 4096
#define EPS    1e-6f

#define CH     32            // chunk length
#define NCH    (LL/CH)       // 64 chunks

// ---------------- scratch (static device arrays; no allocations) -------------
__device__ float          g_xp  [BL * EE];              // after in-proj (fp32)
__device__ float          g_hloc[BB * NCH * DSTATE * EE];   // per-chunk final g
__device__ float          g_hin [BB * NCH * DSTATE * EE];   // per-chunk incoming g
__device__ __nv_bfloat16  g_xnh [BL * DIM];             // rmsnorm out hi
__device__ __nv_bfloat16  g_xnl [BL * DIM];             // rmsnorm out lo
__device__ __nv_bfloat16  g_winh[EE * DIM];
__device__ __nv_bfloat16  g_winl[EE * DIM];
__device__ __nv_bfloat16  g_wouth[DIM * EE];
__device__ __nv_bfloat16  g_woutl[DIM * EE];
__device__ __nv_bfloat16  g_yh  [BL * EE];              // final scan out hi
__device__ __nv_bfloat16  g_yl  [BL * EE];              // final scan out lo

__device__ __forceinline__ float sigmoidf_(float v) {
    return 1.0f / (1.0f + expf(-v));
}

__device__ __forceinline__ uint32_t smem_u32_(const void* p) {
    uint32_t a;
    asm("{ .reg .u64 t; cvta.to.shared.u64 t, %1; cvt.u32.u64 %0, t; }"
        : "=r"(a) : "l"(p));
    return a;
}

// ---------------- rmsnorm (writes bf16 hi/lo split) --------------------------
__global__ void rmsnorm_kernel(const float* __restrict__ x,
                               const float* __restrict__ gamma,
                               __nv_bfloat16* __restrict__ xnh,
                               __nv_bfloat16* __restrict__ xnl)
{
    const int row = blockIdx.x;
    const float* xr = x + (size_t)row * DIM;

    float v0 = xr[threadIdx.x];
    float v1 = xr[threadIdx.x + 256];
    float v2 = xr[threadIdx.x + 512];
    float ss = v0 * v0 + v1 * v1 + v2 * v2;

    #pragma unroll
    for (int o = 16; o > 0; o >>= 1)
        ss += __shfl_xor_sync(0xffffffffu, ss, o);

    __shared__ float warp_s[8];
    int wid = threadIdx.x >> 5, lane = threadIdx.x & 31;
    if (lane == 0) warp_s[wid] = ss;
    __syncthreads();
    if (wid == 0) {
        float t = (lane < 8) ? warp_s[lane] : 0.f;
        #pragma unroll
        for (int o = 4; o > 0; o >>= 1)
            t += __shfl_xor_sync(0xffffffffu, t, o);
        if (lane == 0) warp_s[0] = t;
    }
    __syncthreads();
    float rms = sqrtf(warp_s[0] * (1.0f / DIM));
    float inv = 1.0f / (rms + EPS);

    #pragma unroll
    for (int k = 0; k < 3; k++) {
        int i = threadIdx.x + k * 256;
        float v = (k == 0) ? v0 : (k == 1) ? v1 : v2;
        float o = gamma[i] * v * inv;
        __nv_bfloat16 h = __float2bfloat16(o);
        xnh[(size_t)row * DIM + i] = h;
        xnl[(size_t)row * DIM + i] = __float2bfloat16(o - __bfloat162float(h));
    }
}

// ---------------- weight conversion fp32 -> bf16 hi/lo (float4) --------------
__global__ void convert_w_kernel(const float* __restrict__ W_in,
                                 const float* __restrict__ W_out,
                                 __nv_bfloat16* __restrict__ winh,
                                 __nv_bfloat16* __restrict__ winl,
                                 __nv_bfloat16* __restrict__ wouth,
                                 __nv_bfloat16* __restrict__ woutl)
{
    const int SZ = EE * DIM;                 // multiple of 4
    int q = blockIdx.x * blockDim.x + threadIdx.x;   // float4 index
    if (q >= (2 * SZ) / 4) return;
    int j4 = q * 4;
    const float* s; __nv_bfloat16 *dh, *dl; int j;
    if (j4 < SZ) { s = W_in;  j = j4;      dh = winh;  dl = winl;  }
    else         { s = W_out; j = j4 - SZ; dh = wouth; dl = woutl; }

    float4 v = *(const float4*)&s[j];
    __nv_bfloat16 h0 = __float2bfloat16(v.x);
    __nv_bfloat16 h1 = __float2bfloat16(v.y);
    __nv_bfloat16 h2 = __float2bfloat16(v.z);
    __nv_bfloat16 h3 = __float2bfloat16(v.w);
    __nv_bfloat16 hv[4] = { h0, h1, h2, h3 };
    __nv_bfloat16 lv[4] = {
        __float2bfloat16(v.x - __bfloat162float(h0)),
        __float2bfloat16(v.y - __bfloat162float(h1)),
        __float2bfloat16(v.z - __bfloat162float(h2)),
        __float2bfloat16(v.w - __bfloat162float(h3))
    };
    *(uint2*)&dh[j] = *(const uint2*)hv;
    *(uint2*)&dl[j] = *(const uint2*)lv;
}

// ======================= HMMA (mma.sync) GEMM ================================
// C[M,N] = A[M,K] * B[N,K]^T + bias (+resid), A/B given as bf16 hi/lo pairs;
// 3 products: Ah*Bh + Ah*Bl + Al*Bh (fp32 accumulate).
// CTA tile 64x128x32, 256 threads, 8 warps (2x4), warp tile 32x32.
// 16B cp.async, 2-stage, 61440B smem -> 3 CTAs/SM (load balance).

#define BKT    32
#define PADR   40                      // bf16 per row (32 data + 8 pad) -> 80B rows
#define APLANE (64 * PADR)             // 2560 bf16 (A planes: 64 rows)
#define BPLANE (128 * PADR)            // 5120 bf16 (B planes: 128 rows)
#define STAGE  (2 * APLANE + 2 * BPLANE)   // 15360 bf16 = 30720 B
#define SMEM_GEMM (2 * STAGE * 2)      // 61440 bytes

__device__ __forceinline__ void mma16816(float* d, const uint32_t* a, const uint32_t* b) {
    asm volatile(
        "mma.sync.aligned.m16n8k16.row.col.f32.bf16.bf16.f32 "
        "{%0,%1,%2,%3}, {%4,%5,%6,%7}, {%8,%9}, {%0,%1,%2,%3};"
        : "+f"(d[0]), "+f"(d[1]), "+f"(d[2]), "+f"(d[3])
        : "r"(a[0]), "r"(a[1]), "r"(a[2]), "r"(a[3]), "r"(b[0]), "r"(b[1]));
}

__device__ __forceinline__ void ldsm4(uint32_t* r, uint32_t addr) {
    asm volatile("ldmatrix.sync.aligned.m8n8.x4.shared.b16 {%0,%1,%2,%3}, [%4];"
                 : "=r"(r[0]), "=r"(r[1]), "=r"(r[2]), "=r"(r[3]) : "r"(addr));
}

#define CP_ASYNC16(s, g) asm volatile("cp.async.cg.shared.global [%0], [%1], 16;" :: "r"(s), "l"(g))
#define CP_COMMIT()      asm volatile("cp.async.commit_group;")
#define CP_WAIT1()       asm volatile("cp.async.wait_group 1;")

template<bool RESID>
__global__ __launch_bounds__(256, 3)
void gemm_mma_kernel(const __nv_bfloat16* __restrict__ Ah,
                     const __nv_bfloat16* __restrict__ Al,
                     const __nv_bfloat16* __restrict__ Bh,
                     const __nv_bfloat16* __restrict__ Bl,
                     const float* __restrict__ bias,
                     const float* __restrict__ resid,
                     float* __restrict__ Cout,
                     int N, int K)
{
    extern __shared__ __nv_bfloat16 sm[];       // 61440 bytes dynamic
    const uint32_t sm32 = smem_u32_(sm);
    const int tid  = threadIdx.x;
    const int wid  = tid >> 5, lane = tid & 31;
    const int g    = lane >> 2;
    const int t2   = (lane & 3) * 2;
    const int brow = blockIdx.y * 64, bcol = blockIdx.x * 128;
    const int warp_m = (wid >> 2) * 32;   // 0 or 32
    const int warp_n = (wid & 3) * 32;    // 0,32,64,96

    const __nv_bfloat16* gptr[4] = { Ah, Al, Bh, Bl };

    // per-lane ldmatrix byte offsets (within plane)
    const int arow  = (lane & 7) + 8 * ((lane >> 3) & 1);
    const int akofs = 8 * (lane >> 4);
    const uint32_t a_off = (uint32_t)((warp_m + arow) * PADR + akofs) * 2;
    const int browl = (lane & 7) + 8 * (lane >> 4);
    const int bkofs = 8 * ((lane >> 3) & 1);
    const uint32_t b_off = (uint32_t)((warp_n + browl) * PADR + bkofs) * 2;

    float acc[2][4][4];
    #pragma unroll
    for (int mt = 0; mt < 2; mt++)
        #pragma unroll
        for (int nt = 0; nt < 4; nt++)
            #pragma unroll
            for (int q = 0; q < 4; q++) acc[mt][nt][q] = 0.f;

    // stage loader: A planes 64 rows, B planes 128 rows, 64B data/row.
    // 1536 16B-chunks total -> 6 per thread.
    auto issue = [&](int st, int kt) {
        uint32_t sb = sm32 + (uint32_t)st * STAGE * 2;
        #pragma unroll
        for (int q = 0; q < 6; q++) {
            int ch = tid + q * 256;              // 0..1535
            int r, rbase;
            uint32_t pofs;
            const __nv_bfloat16* gp;
            if (ch < 512) {                      // Ah / Al: 256 chunks each
                int pa = ch >> 8;                // 0=Ah 1=Al
                int rc = ch & 255;
                r = rc >> 2;
                pofs = (uint32_t)(pa * APLANE);
                gp = gptr[pa];
                rbase = brow;
            } else {                             // Bh / Bl: 512 chunks each
                int cb = ch - 512;
                int pb = cb >> 9;                // 0=Bh 1=Bl
                int rc = cb & 511;
                r = rc >> 2;
                pofs = (uint32_t)(2 * APLANE + pb * BPLANE);
                gp = gptr[2 + pb];
                rbase = bcol;
            }
            int c = (ch & 3) * 8;                // bf16 col 0,8,16,24
            uint32_t sa = sb + (pofs + (uint32_t)(r * PADR + c)) * 2;
            const __nv_bfloat16* ga = gp + (size_t)(rbase + r) * K + kt + c;
            CP_ASYNC16(sa, ga);
        }
        CP_COMMIT();
    };

    const int NK = K / BKT;
    issue(0, 0);
    issue(1, BKT);
    CP_WAIT1();
    __syncthreads();

    for (int i = 0; i < NK; i++) {
        const int st = i & 1;
        const uint32_t sbase = sm32 + (uint32_t)st * STAGE * 2;

        #pragma unroll
        for (int kk = 0; kk < BKT; kk += 16) {
            const uint32_t kb = (uint32_t)kk * 2;
            uint32_t ah[2][4], al[2][4], bh[2][4], bl[2][4];
            #pragma unroll
            for (int mt = 0; mt < 2; mt++) {
                uint32_t ad = sbase + a_off + (uint32_t)(mt * 16 * PADR) * 2 + kb;
                ldsm4(ah[mt], ad);
                ldsm4(al[mt], ad + (uint32_t)APLANE * 2);
            }
            #pragma unroll
            for (int ntp = 0; ntp < 2; ntp++) {
                uint32_t bd = sbase + b_off
                            + (uint32_t)(2 * APLANE + ntp * 16 * PADR) * 2 + kb;
                ldsm4(bh[ntp], bd);
                ldsm4(bl[ntp], bd + (uint32_t)BPLANE * 2);
            }

            #pragma unroll
            for (int mt = 0; mt < 2; mt++)
                #pragma unroll
                for (int nt = 0; nt < 4; nt++) {
                    const uint32_t* fh = &bh[nt >> 1][(nt & 1) * 2];
                    const uint32_t* fl = &bl[nt >> 1][(nt & 1) * 2];
                    mma16816(acc[mt][nt], ah[mt], fh);
                    mma16816(acc[mt][nt], ah[mt], fl);
                    mma16816(acc[mt][nt], al[mt], fh);
                }
        }

        __syncthreads();
        if (i + 2 < NK) issue(st, (i + 2) * BKT);
        else            CP_COMMIT();
        CP_WAIT1();
        __syncthreads();
    }

    #pragma unroll
    for (int mt = 0; mt < 2; mt++) {
        int r0 = brow + warp_m + mt * 16 + g;
        #pragma unroll
        for (int nt = 0; nt < 4; nt++) {
            int c = bcol + warp_n + nt * 8 + t2;
            float2 bv = *(const float2*)&bias[c];
            float2 o0, o1;
            o0.x = acc[mt][nt][0] + bv.x;
            o0.y = acc[mt][nt][1] + bv.y;
            o1.x = acc[mt][nt][2] + bv.x;
            o1.y = acc[mt][nt][3] + bv.y;
            if (RESID) {
                float2 rv0 = *(const float2*)&resid[(size_t)r0 * N + c];
                float2 rv1 = *(const float2*)&resid[(size_t)(r0 + 8) * N + c];
                o0.x += rv0.x; o0.y += rv0.y;
                o1.x += rv1.x; o1.y += rv1.y;
            }
            *(float2*)&Cout[(size_t)r0 * N + c]       = o0;
            *(float2*)&Cout[(size_t)(r0 + 8) * N + c] = o1;
        }
    }
}

// ---------------- K1: per-chunk final g-states (conv fused) ------------------
__global__ __launch_bounds__(256)
void scan_state_kernel(const float* __restrict__ xp,
                       const float* __restrict__ A,
                       const float* __restrict__ convw,
                       float* __restrict__ hloc)
{
    int tid = blockIdx.x * blockDim.x + threadIdx.x;   // b*NCH*EE + c*EE + e
    int e  = tid % EE;
    int bc = tid / EE;
    int c  = bc % NCH;
    int b  = bc / NCH;

    float sA[DSTATE], g[DSTATE];
    #pragma unroll
    for (int n = 0; n < DSTATE; n++) {
        sA[n] = sigmoidf_(A[e * DSTATE + n]);
        g[n] = 0.f;
    }
    float w0 = convw[e * 4 + 0];
    float w1 = convw[e * 4 + 1];
    float w2 = convw[e * 4 + 2];
    float w3 = convw[e * 4 + 3];

    const int t0 = c * CH;
    const float* xb = xp + (size_t)b * LL * EE + e;
    float xm1 = (t0 >= 1) ? xb[(size_t)(t0 - 1) * EE] : 0.f;
    float xm2 = (t0 >= 2) ? xb[(size_t)(t0 - 2) * EE] : 0.f;
    float xm3 = (t0 >= 3) ? xb[(size_t)(t0 - 3) * EE] : 0.f;

    const float* xq = xb + (size_t)t0 * EE;

    #pragma unroll
    for (int tb = 0; tb < CH; tb += 8) {
        float xv[8];
        #pragma unroll
        for (int j = 0; j < 8; j++)
            xv[j] = xq[(size_t)(tb + j) * EE];

        #pragma unroll
        for (int j = 0; j < 8; j++) {
            float xcv = xv[j] * w3 + xm1 * w2 + xm2 * w1 + xm3 * w0;
            xm3 = xm2; xm2 = xm1; xm1 = xv[j];
            #pragma unroll
            for (int n = 0; n < DSTATE; n++)
                g[n] = fmaf(sA[n], g[n], xcv);
        }
    }

    float* hp = hloc + (((size_t)b * NCH + c) * DSTATE) * EE + e;
    #pragma unroll
    for (int n = 0; n < DSTATE; n++)
        hp[(size_t)n * EE] = g[n];
}

// ---------------- K2: combine chunk g-states sequentially --------------------
__global__ void chunk_combine_kernel(const float* __restrict__ hloc,
                                     const float* __restrict__ A,
                                     float* __restrict__ hin)
{
    int tid = blockIdx.x * blockDim.x + threadIdx.x;   // b*DSTATE*EE + n*EE + e
    int e  = tid % EE;
    int bn = tid / EE;
    int n  = bn % DSTATE;
    int b  = bn / DSTATE;

    float sA = sigmoidf_(A[e * DSTATE + n]);
    float pw = sA;
    #pragma unroll
    for (int i = 0; i < 5; i++) pw *= pw;              // sA^32 (CH=32)

    size_t base = ((size_t)b * NCH * DSTATE + n) * EE + e;
    const size_t cstride = (size_t)DSTATE * EE;

    float h = 0.f;
    #pragma unroll
    for (int c = 0; c < NCH; c++) {
        hin[base + c * cstride] = h;
        h = fmaf(pw, h, hloc[base + c * cstride]);
    }
}

// ---------------- K3: full g-scan from hin, y = sum sCB*g, bf16 split --------
__global__ __launch_bounds__(256)
void scan_out_kernel(const float* __restrict__ xp,
                     const float* __restrict__ hin,
                     const float* __restrict__ A,
                     const float* __restrict__ Bp,
                     const float* __restrict__ C,
                     const float* __restrict__ convw,
                     __nv_bfloat16* __restrict__ yh,
                     __nv_bfloat16* __restrict__ yl)
{
    int tid = blockIdx.x * blockDim.x + threadIdx.x;   // b*NCH*EE + c*EE + e
    int e  = tid % EE;
    int bc = tid / EE;
    int c  = bc % NCH;
    int b  = bc / NCH;

    float sA[DSTATE], sCB[DSTATE], g[DSTATE];
    const float* hp = hin + (((size_t)b * NCH + c) * DSTATE) * EE + e;
    #pragma unroll
    for (int n = 0; n < DSTATE; n++) {
        sA[n]  = sigmoidf_(A[e * DSTATE + n]);
        sCB[n] = sigmoidf_(C[e * DSTATE + n]) * sigmoidf_(Bp[e * DSTATE + n]);
        g[n]   = (c > 0) ? hp[(size_t)n * EE] : 0.f;
    }
    float w0 = convw[e * 4 + 0];
    float w1 = convw[e * 4 + 1];
    float w2 = convw[e * 4 + 2];
    float w3 = convw[e * 4 + 3];

    const int t0 = c * CH;
    const float* xb = xp + (size_t)b * LL * EE + e;
    float xm1 = (t0 >= 1) ? xb[(size_t)(t0 - 1) * EE] : 0.f;
    float xm2 = (t0 >= 2) ? xb[(size_t)(t0 - 2) * EE] : 0.f;
    float xm3 = (t0 >= 3) ? xb[(size_t)(t0 - 3) * EE] : 0.f;

    const float* xq = xb + (size_t)t0 * EE;
    size_t obase = ((size_t)b * LL + t0) * EE + e;
    __nv_bfloat16* yhb = yh + obase;
    __nv_bfloat16* ylb = yl + obase;

    #pragma unroll
    for (int tb = 0; tb < CH; tb += 8) {
        float xv[8];
        #pragma unroll
        for (int j = 0; j < 8; j++)
            xv[j] = xq[(size_t)(tb + j) * EE];

        #pragma unroll
        for (int j = 0; j < 8; j++) {
            float xcv = xv[j] * w3 + xm1 * w2 + xm2 * w1 + xm3 * w0;
            xm3 = xm2; xm2 = xm1; xm1 = xv[j];

            float a0 = 0.f, a1 = 0.f, a2 = 0.f, a3 = 0.f;
            #pragma unroll
            for (int n = 0; n < DSTATE; n += 4) {
                g[n + 0] = fmaf(sA[n + 0], g[n + 0], xcv);
                g[n + 1] = fmaf(sA[n + 1], g[n + 1], xcv);
                g[n + 2] = fmaf(sA[n + 2], g[n + 2], xcv);
                g[n + 3] = fmaf(sA[n + 3], g[n + 3], xcv);
                a0 = fmaf(sCB[n + 0], g[n + 0], a0);
                a1 = fmaf(sCB[n + 1], g[n + 1], a1);
                a2 = fmaf(sCB[n + 2], g[n + 2], a2);
                a3 = fmaf(sCB[n + 3], g[n + 3], a3);
            }
            float v = (a0 + a1) + (a2 + a3);
            __nv_bfloat16 hv = __float2bfloat16(v);
            yhb[(size_t)(tb + j) * EE] = hv;
            ylb[(size_t)(tb + j) * EE] = __float2bfloat16(v - __bfloat162float(hv));
        }
    }
}

// ---------------- launch -----------------------------------------------------
extern "C" void kernel_launch(void* const* d_in, const int* in_sizes, int n_in,
                              void* d_out, int out_size)
{
    const float* x      = (const float*)d_in[0];
    const float* gamma  = (const float*)d_in[1];
    const float* W_in   = (const float*)d_in[2];
    const float* b_in   = (const float*)d_in[3];
    const float* conv_w = (const float*)d_in[4];
    const float* A      = (const float*)d_in[5];
    const float* Bp     = (const float*)d_in[6];
    const float* C      = (const float*)d_in[7];
    const float* W_out  = (const float*)d_in[8];
    const float* b_out  = (const float*)d_in[9];
    float* out = (float*)d_out;

    float *xp, *hloc, *hin;
    __nv_bfloat16 *xnh, *xnl, *winh, *winl, *wouth, *woutl, *yh, *yl;
    cudaGetSymbolAddress((void**)&xp,    g_xp);
    cudaGetSymbolAddress((void**)&hloc,  g_hloc);
    cudaGetSymbolAddress((void**)&hin,   g_hin);
    cudaGetSymbolAddress((void**)&xnh,   g_xnh);
    cudaGetSymbolAddress((void**)&xnl,   g_xnl);
    cudaGetSymbolAddress((void**)&winh,  g_winh);
    cudaGetSymbolAddress((void**)&winl,  g_winl);
    cudaGetSymbolAddress((void**)&wouth, g_wouth);
    cudaGetSymbolAddress((void**)&woutl, g_woutl);
    cudaGetSymbolAddress((void**)&yh,    g_yh);
    cudaGetSymbolAddress((void**)&yl,    g_yl);

    // idempotent, capture-safe, no static state
    cudaFuncSetAttribute(gemm_mma_kernel<false>,
                         cudaFuncAttributeMaxDynamicSharedMemorySize, SMEM_GEMM);
    cudaFuncSetAttribute(gemm_mma_kernel<true>,
                         cudaFuncAttributeMaxDynamicSharedMemorySize, SMEM_GEMM);

    // 1. rmsnorm -> bf16 hi/lo
    rmsnorm_kernel<<<BL, 256>>>(x, gamma, xnh, xnl);

    // 1b. convert weights -> bf16 hi/lo (float4)
    {
        int qtot = (2 * EE * DIM) / 4;                 // 589824
        convert_w_kernel<<<(qtot + 255) / 256, 256>>>(W_in, W_out,
                                                      winh, winl, wouth, woutl);
    }

    // 2. in-proj (HMMA): xp = xn @ W_in^T + b_in
    {
        dim3 grid(EE / 128, BL / 64);
        gemm_mma_kernel<false><<<grid, 256, SMEM_GEMM>>>(xnh, xnl, winh, winl,
                                                         b_in, nullptr, xp, EE, DIM);
    }

    // 3. chunked g-scan (conv fused)
    {
        int threads = BB * NCH * EE;                   // 196608
        scan_state_kernel<<<threads / 256, 256>>>(xp, A, conv_w, hloc);
    }
    {
        int threads = BB * DSTATE * EE;                // 49152
        chunk_combine_kernel<<<threads / 256, 256>>>(hloc, A, hin);
    }
    {
        int threads = BB * NCH * EE;
        scan_out_kernel<<<threads / 256, 256>>>(xp, hin, A, Bp, C, conv_w, yh, yl);
    }

    // 4. out-proj + residual (HMMA): out = y @ W_out^T + b_out + x
    {
        dim3 grid(DIM / 128, BL / 64);
        gemm_mma_kernel<true><<<grid, 256, SMEM_GEMM>>>(yh, yl, wouth, woutl,
                                                        b_out, x, out, DIM, EE);
    }
}